// round 17
// baseline (speedup 1.0000x reference)
#include <cuda_runtime.h>
#include <cuda_fp16.h>
#include <math.h>
#include <stdint.h>

#define DIM   1024
#define NH    16
#define NKV   4
#define HD    64
#define WIN   512
#define BB    2
#define SS    2048
#define TT    (BB*SS)
#define QKVW  1536
#define GK    1024
#define LOG2E 1.4426950408889634f

// ---------------- scratch ----------------
__device__ __half g_qkvh[(size_t)TT * QKVW];
__device__ __half g_ah[(size_t)TT * DIM];
__device__ __half g_wh[(size_t)2560 * DIM];
__device__ __half g_qh[(size_t)TT * DIM];
__device__ __half g_kh[(size_t)TT * 256];
__device__ __half g_vh[(size_t)TT * 256];
#define WO_ROW 1536

// ---------------- PTX helpers ----------------
__device__ __forceinline__ uint32_t smem_u32(const void* p) {
    uint32_t a;
    asm("{ .reg .u64 t; cvta.to.shared.u64 t, %1; cvt.u32.u64 %0, t; }" : "=r"(a) : "l"(p));
    return a;
}
__device__ __forceinline__ void cp16(uint32_t s, const void* g) {
    asm volatile("{ .reg .u64 gg; cvta.to.global.u64 gg, %1; cp.async.cg.shared.global [%0], [gg], 16; }"
                 :: "r"(s), "l"(g) : "memory");
}
__device__ __forceinline__ void cp_commit() { asm volatile("cp.async.commit_group;" ::: "memory"); }
template <int N>
__device__ __forceinline__ void cp_wait() { asm volatile("cp.async.wait_group %0;" :: "n"(N) : "memory"); }

__device__ __forceinline__ uint32_t packh(float lo, float hi) {
    uint32_t r;
    asm("cvt.rn.f16x2.f32 %0, %1, %2;" : "=r"(r) : "f"(hi), "f"(lo));
    return r;
}
__device__ __forceinline__ float ex2(float x) {
    float y;
    asm("ex2.approx.ftz.f32 %0, %1;" : "=f"(y) : "f"(x));
    return y;
}

#define MMA_F16(c0,c1,c2,c3, a0,a1,a2,a3, b0,b1) \
    asm volatile("mma.sync.aligned.m16n8k16.row.col.f32.f16.f16.f32 " \
                 "{%0,%1,%2,%3}, {%4,%5,%6,%7}, {%8,%9}, {%0,%1,%2,%3};" \
                 : "+f"(c0), "+f"(c1), "+f"(c2), "+f"(c3) \
                 : "r"(a0), "r"(a1), "r"(a2), "r"(a3), "r"(b0), "r"(b1))

#define LDMX4(r0,r1,r2,r3, addr) \
    asm volatile("ldmatrix.sync.aligned.m8n8.x4.shared.b16 {%0,%1,%2,%3}, [%4];" \
                 : "=r"(r0), "=r"(r1), "=r"(r2), "=r"(r3) : "r"(addr))
#define LDMX4T(r0,r1,r2,r3, addr) \
    asm volatile("ldmatrix.sync.aligned.m8n8.x4.trans.shared.b16 {%0,%1,%2,%3}, [%4];" \
                 : "=r"(r0), "=r"(r1), "=r"(r2), "=r"(r3) : "r"(addr))

// ---------------- fused splits ----------------
__global__ __launch_bounds__(256) void split_all(
    const float* __restrict__ x,
    const float* __restrict__ wq, const float* __restrict__ wk,
    const float* __restrict__ wv, const float* __restrict__ wo)
{
    int i = blockIdx.x * 256 + threadIdx.x;
    if (i < 1048576) {
        float4 v = ((const float4*)x)[i];
        union { __half b[4]; uint2 u; } H;
        H.b[0] = __float2half(v.x); H.b[1] = __float2half(v.y);
        H.b[2] = __float2half(v.z); H.b[3] = __float2half(v.w);
        ((uint2*)g_ah)[i] = H.u;
    } else {
        int j = i - 1048576;
        const float* src;
        int local;
        if (j < 262144)      { src = wq; local = j; }
        else if (j < 327680) { src = wk; local = j - 262144; }
        else if (j < 393216) { src = wv; local = j - 327680; }
        else                 { src = wo; local = j - 393216; }
        float4 v = ((const float4*)src)[local];
        union { __half b[4]; uint2 u; } H;
        H.b[0] = __float2half(v.x); H.b[1] = __float2half(v.y);
        H.b[2] = __float2half(v.z); H.b[3] = __float2half(v.w);
        ((uint2*)g_wh)[j] = H.u;
    }
}

// ---------------- HMMA fp16 GEMM: 128x64 tile, BK=64, 2-stage, 3 CTAs/SM ----------------
#define BKC 64
#define NCHG (GK / BKC)          // 16
#define SROWG 72                 // halves per row
#define ROWS_S 192               // 128 A rows + 64 B rows
#define STAGEG (ROWS_S * SROWG)  // halves per stage
#define GEMM_SMEM (2 * STAGEG * 2)   // 55296 bytes

__global__ __launch_bounds__(256, 3) void hmma_gemm(
    const __half* __restrict__ ah, const __half* __restrict__ bh,
    void* __restrict__ Cout, int ldc, int coff, int out_half)
{
    extern __shared__ char smraw[];
    const uint32_t smb = smem_u32(smraw);

    const int tid = threadIdx.x;
    const int wid = tid >> 5;
    const int lid = tid & 31;
    const int wm = wid & 1;          // 0..1 -> 64 M rows each
    const int wn = wid >> 1;         // 0..3 -> 16 N rows each
    const int m0 = blockIdx.y * 128;
    const int n0 = blockIdx.x * 64;

    const __half* abase = ah + (size_t)m0 * GK;
    const __half* bbase = bh + (size_t)n0 * GK;

    auto load_stage = [&](int kc, int stg) {
        const uint32_t base = smb + (uint32_t)stg * (STAGEG * 2);
#pragma unroll
        for (int i = 0; i < 6; i++) {
            int id = tid + 256 * i;          // 0..1535
            int row = id >> 3, seg = id & 7; // row 0..191
            const __half* src = (row < 128)
                ? abase + (size_t)row * GK + kc + seg * 8
                : bbase + (size_t)(row - 128) * GK + kc + seg * 8;
            cp16(base + (uint32_t)(row * SROWG + seg * 8) * 2, src);
        }
        cp_commit();
    };

    float acc[4][2][4];
#pragma unroll
    for (int i = 0; i < 4; i++)
#pragma unroll
        for (int j = 0; j < 2; j++)
#pragma unroll
            for (int k = 0; k < 4; k++) acc[i][j][k] = 0.f;

    const uint32_t frag_off =
        (uint32_t)((((lid & 7) + ((lid >> 3) & 1) * 8) * SROWG + (lid >> 4) * 8) * 2);

    load_stage(0, 0);
    load_stage(BKC, 1);

    for (int c = 0; c < NCHG; c++) {
        if (c < NCHG - 1) cp_wait<1>(); else cp_wait<0>();
        __syncthreads();

        const uint32_t sbase = smb + (uint32_t)(c & 1) * (STAGEG * 2);

#pragma unroll
        for (int ks = 0; ks < 4; ks++) {
            uint32_t Ah[4][4], Bf[4];
#pragma unroll
            for (int mf = 0; mf < 4; mf++) {
                uint32_t aaddr = sbase +
                    (uint32_t)(((wm * 64 + mf * 16) * SROWG + ks * 16) * 2) + frag_off;
                LDMX4(Ah[mf][0], Ah[mf][1], Ah[mf][2], Ah[mf][3], aaddr);
            }
            {
                uint32_t baddr = sbase +
                    (uint32_t)(((128 + wn * 16) * SROWG + ks * 16) * 2) + frag_off;
                LDMX4(Bf[0], Bf[1], Bf[2], Bf[3], baddr);
            }

#pragma unroll
            for (int mf = 0; mf < 4; mf++) {
                MMA_F16(acc[mf][0][0], acc[mf][0][1], acc[mf][0][2], acc[mf][0][3],
                        Ah[mf][0], Ah[mf][1], Ah[mf][2], Ah[mf][3], Bf[0], Bf[2]);
                MMA_F16(acc[mf][1][0], acc[mf][1][1], acc[mf][1][2], acc[mf][1][3],
                        Ah[mf][0], Ah[mf][1], Ah[mf][2], Ah[mf][3], Bf[1], Bf[3]);
            }
        }

        __syncthreads();
        if (c + 2 < NCHG) load_stage((c + 2) * BKC, c & 1);
    }

    const int r2 = lid >> 2;
    const int c2 = (lid & 3) * 2;
    if (out_half) {
        __half* C = (__half*)Cout;
#pragma unroll
        for (int mf = 0; mf < 4; mf++) {
            const int row = m0 + wm * 64 + mf * 16 + r2;
#pragma unroll
            for (int nf = 0; nf < 2; nf++) {
                __half* cp0 = C + (size_t)row * ldc + coff + n0 + wn * 16 + nf * 8 + c2;
                *(uint32_t*)cp0 = packh(acc[mf][nf][0], acc[mf][nf][1]);
                *(uint32_t*)(cp0 + 8 * (size_t)ldc) = packh(acc[mf][nf][2], acc[mf][nf][3]);
            }
        }
    } else {
        float* C = (float*)Cout;
#pragma unroll
        for (int mf = 0; mf < 4; mf++) {
            const int row = m0 + wm * 64 + mf * 16 + r2;
#pragma unroll
            for (int nf = 0; nf < 2; nf++) {
                float* cp0 = C + (size_t)row * ldc + coff + n0 + wn * 16 + nf * 8 + c2;
                *(float2*)cp0 = make_float2(acc[mf][nf][0], acc[mf][nf][1]);
                *(float2*)(cp0 + 8 * (size_t)ldc) = make_float2(acc[mf][nf][2], acc[mf][nf][3]);
            }
        }
    }
}

// ---------------- fused q-rms + k-rms + v relayout (fp16 input) ----------------
__global__ __launch_bounds__(256) void prep_qkv(
    const float* __restrict__ qw, const float* __restrict__ kw)
{
    const int t = blockIdx.x;
    const int b = t >> 11, s = t & (SS - 1);
    const __half* row = g_qkvh + (size_t)t * QKVW;
    const int tid = threadIdx.x;

    uint2 qu = *(const uint2*)(row + tid * 4);
    float2 q01 = __half22float2(*(__half2*)&qu.x);
    float2 q23 = __half22float2(*(__half2*)&qu.y);
    float ssq = q01.x * q01.x;
    ssq = fmaf(q01.y, q01.y, ssq);
    ssq = fmaf(q23.x, q23.x, ssq);
    ssq = fmaf(q23.y, q23.y, ssq);

    float2 k01 = make_float2(0.f, 0.f), k23 = make_float2(0.f, 0.f);
    uint2 vu = make_uint2(0u, 0u);
    float ssk = 0.f;
    if (tid < 64) {
        uint2 ku = *(const uint2*)(row + 1024 + tid * 4);
        k01 = __half22float2(*(__half2*)&ku.x);
        k23 = __half22float2(*(__half2*)&ku.y);
        ssk = k01.x * k01.x;
        ssk = fmaf(k01.y, k01.y, ssk);
        ssk = fmaf(k23.x, k23.x, ssk);
        ssk = fmaf(k23.y, k23.y, ssk);
    } else if (tid < 128) {
        vu = *(const uint2*)(row + 1280 + (tid - 64) * 4);
    }

#pragma unroll
    for (int o = 16; o > 0; o >>= 1) {
        ssq += __shfl_xor_sync(0xffffffffu, ssq, o);
        ssk += __shfl_xor_sync(0xffffffffu, ssk, o);
    }

    __shared__ float redq[8], redk[8];
    __shared__ float sclq_s, sclk_s;
    if ((tid & 31) == 0) { redq[tid >> 5] = ssq; redk[tid >> 5] = ssk; }
    __syncthreads();
    if (tid == 0) {
        float tq = 0.f, tk = 0.f;
#pragma unroll
        for (int i = 0; i < 8; i++) { tq += redq[i]; tk += redk[i]; }
        sclq_s = rsqrtf(tq * (1.f / 1024.f) + 1e-6f) * (0.125f * LOG2E);
        sclk_s = rsqrtf(tk * (1.f / 256.f) + 1e-6f);
    }
    __syncthreads();
    const float sclq = sclq_s, sclk = sclk_s;

    {
        float4 qwv = *(const float4*)(qw + tid * 4);
        float v0 = q01.x * sclq * qwv.x;
        float v1 = q01.y * sclq * qwv.y;
        float v2 = q23.x * sclq * qwv.z;
        float v3 = q23.y * sclq * qwv.w;
        int idx = tid * 4;
        int head = idx >> 6, d = idx & 63;
        size_t off = ((size_t)(b * NH + head) * SS + s) * 64 + d;
        *(uint2*)(g_qh + off) = make_uint2(packh(v0, v1), packh(v2, v3));
    }

    if (tid < 64) {
        int idx = tid * 4;
        int kv = idx >> 6, d = idx & 63;
        float4 kwv = *(const float4*)(kw + idx);
        float v0 = k01.x * sclk * kwv.x;
        float v1 = k01.y * sclk * kwv.y;
        float v2 = k23.x * sclk * kwv.z;
        float v3 = k23.y * sclk * kwv.w;
        size_t off = ((size_t)(b * NKV + kv) * SS + s) * 64 + d;
        *(uint2*)(g_kh + off) = make_uint2(packh(v0, v1), packh(v2, v3));
    } else if (tid < 128) {
        int idx = (tid - 64) * 4;
        int kv = idx >> 6, d = idx & 63;
        size_t off = ((size_t)(b * NKV + kv) * SS + s) * 64 + d;
        *(uint2*)(g_vh + off) = vu;
    }
}

// ---------------- tensor-core attention (unchanged math; longest-first scheduling) ----------------
#define TILEB 9216
#define VOFF  18432
#define STAGEB 36864
#define ATT_SMEM (2 * STAGEB)

__global__ __launch_bounds__(256, 2) void attn_tc()
{
    extern __shared__ char asm_[];
    const uint32_t smb = smem_u32(asm_);

    const int tid = threadIdx.x;
    const int wid = tid >> 5;
    const int lid = tid & 31;
    // longest-first: reverse qtile mapping so high-qstart (more windows) CTAs launch first
    const int qstart = (gridDim.x - 1 - blockIdx.x) * 128;
    const int head = blockIdx.y;
    const int b = blockIdx.z;
    const int kvh = head >> 2;

    const int r = lid >> 2;
    const int c2 = (lid & 3) * 2;
    const int qpos0 = qstart + wid * 16 + r;
    const int wqmin = qstart + wid * 16;
    const int wqmax = wqmin + 15;
    const float slope = exp2f(-0.5f * (float)(head + 1)) * LOG2E;

    const __half* qbh = g_qh + ((size_t)(b * NH + head) * SS + qstart + wid * 16) * 64;
    uint32_t Qh[4][4];
#pragma unroll
    for (int ks = 0; ks < 4; ks++) {
        Qh[ks][0] = *(const uint32_t*)(qbh + r * 64 + ks * 16 + c2);
        Qh[ks][1] = *(const uint32_t*)(qbh + (r + 8) * 64 + ks * 16 + c2);
        Qh[ks][2] = *(const uint32_t*)(qbh + r * 64 + ks * 16 + 8 + c2);
        Qh[ks][3] = *(const uint32_t*)(qbh + (r + 8) * 64 + ks * 16 + 8 + c2);
    }

    float O[8][4];
#pragma unroll
    for (int i = 0; i < 8; i++)
#pragma unroll
        for (int j = 0; j < 4; j++) O[i][j] = 0.f;
    float m0 = -INFINITY, m1 = -INFINITY, l0 = 0.f, l1 = 0.f;

    const int kc0 = (qstart >= WIN) ? qstart - WIN : 0;
    const int nwin = (qstart + 128 - kc0) >> 7;

    const int key_ld = tid >> 2;
    const int seg = tid & 3;
    const __half* src_base[2];
    {
        size_t kvb = ((size_t)(b * NKV + kvh) * SS) * 64;
        src_base[0] = g_kh + kvb;
        src_base[1] = g_vh + kvb;
    }
    auto load_window = [&](int kc, int stg) {
        uint32_t sb = smb + stg * STAGEB + key_ld * 144 + seg * 16;
#pragma unroll
        for (int h = 0; h < 2; h++) {
#pragma unroll
            for (int t = 0; t < 2; t++) {
                const __half* src = src_base[t] + (size_t)(kc + h * 64 + key_ld) * 64 + seg * 8;
                cp16(sb + t * VOFF + h * TILEB, src);
                cp16(sb + t * VOFF + h * TILEB + 64, src + 32);
            }
        }
        cp_commit();
    };

    load_window(kc0, 0);
    if (nwin > 1) load_window(kc0 + 128, 1);

    const uint32_t lane_off = (uint32_t)(((lid >> 4) * 8 + (lid & 7)) * 144 + ((lid >> 3) & 1) * 16);

    auto do_chunk = [&](int kc, uint32_t kbase) {
        const bool active = (kc <= wqmax) && (kc + 63 >= wqmin - WIN);
        if (!active) return;
        const bool interior = (kc + 63 <= wqmin) && (kc >= wqmax - WIN);

        bool gok[2];
#pragma unroll
        for (int g = 0; g < 2; g++) {
            int gk0 = kc + g * 32;
            gok[g] = interior || ((gk0 <= wqmax) && (gk0 + 31 >= wqmin - WIN));
        }

        float S[8][4];
#pragma unroll
        for (int i = 0; i < 8; i++)
#pragma unroll
            for (int j = 0; j < 4; j++) S[i][j] = 0.f;

#pragma unroll
        for (int ks = 0; ks < 4; ks++) {
#pragma unroll
            for (int g = 0; g < 2; g++) {
                if (!gok[g]) continue;
                uint32_t kh[2][4];
#pragma unroll
                for (int j = 0; j < 2; j++) {
                    int nfp = g * 2 + j;
                    LDMX4(kh[j][0], kh[j][1], kh[j][2], kh[j][3],
                          kbase + nfp * 2304 + ks * 32 + lane_off);
                }
#pragma unroll
                for (int j = 0; j < 2; j++) {
                    int nf = (g * 2 + j) * 2;
                    MMA_F16(S[nf][0], S[nf][1], S[nf][2], S[nf][3],
                            Qh[ks][0], Qh[ks][1], Qh[ks][2], Qh[ks][3], kh[j][0], kh[j][1]);
                    MMA_F16(S[nf+1][0], S[nf+1][1], S[nf+1][2], S[nf+1][3],
                            Qh[ks][0], Qh[ks][1], Qh[ks][2], Qh[ks][3], kh[j][2], kh[j][3]);
                }
            }
        }

        if (interior) {
#pragma unroll
            for (int nf = 0; nf < 8; nf++) {
                float rel0 = (float)(kc + nf * 8 + c2 - qpos0);
                S[nf][0] = fmaf(slope, rel0,       S[nf][0]);
                S[nf][1] = fmaf(slope, rel0 + 1.f, S[nf][1]);
                S[nf][2] = fmaf(slope, rel0 - 8.f, S[nf][2]);
                S[nf][3] = fmaf(slope, rel0 - 7.f, S[nf][3]);
            }
        } else {
#pragma unroll
            for (int nf = 0; nf < 8; nf++) {
                if (!gok[nf >> 2]) continue;
                int rel0 = kc + nf * 8 + c2 - qpos0;
                int rel2 = rel0 - 8;
                S[nf][0] = (rel0     <= 0 && rel0     >= -WIN) ? fmaf(slope, (float)rel0,     S[nf][0]) : -INFINITY;
                S[nf][1] = (rel0 + 1 <= 0 && rel0 + 1 >= -WIN) ? fmaf(slope, (float)(rel0+1), S[nf][1]) : -INFINITY;
                S[nf][2] = (rel2     <= 0 && rel2     >= -WIN) ? fmaf(slope, (float)rel2,     S[nf][2]) : -INFINITY;
                S[nf][3] = (rel2 + 1 <= 0 && rel2 + 1 >= -WIN) ? fmaf(slope, (float)(rel2+1), S[nf][3]) : -INFINITY;
            }
        }

        float mx0 = -INFINITY, mx1 = -INFINITY;
#pragma unroll
        for (int nf = 0; nf < 8; nf++) {
            if (!gok[nf >> 2]) continue;
            mx0 = fmaxf(mx0, fmaxf(S[nf][0], S[nf][1]));
            mx1 = fmaxf(mx1, fmaxf(S[nf][2], S[nf][3]));
        }
        mx0 = fmaxf(mx0, __shfl_xor_sync(0xffffffffu, mx0, 1));
        mx0 = fmaxf(mx0, __shfl_xor_sync(0xffffffffu, mx0, 2));
        mx1 = fmaxf(mx1, __shfl_xor_sync(0xffffffffu, mx1, 1));
        mx1 = fmaxf(mx1, __shfl_xor_sync(0xffffffffu, mx1, 2));

        float mn0 = fmaxf(fmaxf(m0, mx0), -1e30f);
        float mn1 = fmaxf(fmaxf(m1, mx1), -1e30f);
        float a0 = ex2(m0 - mn0);
        float a1 = ex2(m1 - mn1);
        m0 = mn0; m1 = mn1;
        l0 *= a0; l1 *= a1;
#pragma unroll
        for (int nf = 0; nf < 8; nf++) {
            O[nf][0] *= a0; O[nf][1] *= a0;
            O[nf][2] *= a1; O[nf][3] *= a1;
        }
        if (interior) {
#pragma unroll
            for (int nf = 0; nf < 8; nf++) {
                S[nf][0] = ex2(S[nf][0] - m0);
                S[nf][1] = ex2(S[nf][1] - m0);
                S[nf][2] = ex2(S[nf][2] - m1);
                S[nf][3] = ex2(S[nf][3] - m1);
                l0 += S[nf][0] + S[nf][1];
                l1 += S[nf][2] + S[nf][3];
            }
        } else {
#pragma unroll
            for (int nf = 0; nf < 8; nf++) {
                if (!gok[nf >> 2]) {
                    S[nf][0] = 0.f; S[nf][1] = 0.f; S[nf][2] = 0.f; S[nf][3] = 0.f;
                    continue;
                }
                S[nf][0] = ex2(S[nf][0] - m0);
                S[nf][1] = ex2(S[nf][1] - m0);
                S[nf][2] = ex2(S[nf][2] - m1);
                S[nf][3] = ex2(S[nf][3] - m1);
                l0 += S[nf][0] + S[nf][1];
                l1 += S[nf][2] + S[nf][3];
            }
        }

#pragma unroll
        for (int ks = 0; ks < 4; ks++) {
            int kk0 = kc + ks * 16;
            if (!interior && (kk0 > wqmax || kk0 + 15 < wqmin - WIN)) continue;
            uint32_t ph0 = packh(S[2*ks][0],   S[2*ks][1]);
            uint32_t ph1 = packh(S[2*ks][2],   S[2*ks][3]);
            uint32_t ph2 = packh(S[2*ks+1][0], S[2*ks+1][1]);
            uint32_t ph3 = packh(S[2*ks+1][2], S[2*ks+1][3]);
#pragma unroll
            for (int g = 0; g < 2; g++) {
                uint32_t v[2][4];
#pragma unroll
                for (int j = 0; j < 2; j++) {
                    int nfp = g * 2 + j;
                    LDMX4T(v[j][0], v[j][1], v[j][2], v[j][3],
                           kbase + VOFF + ks * 2304 + nfp * 32 + lane_off);
                }
#pragma unroll
                for (int j = 0; j < 2; j++) {
                    int nf = (g * 2 + j) * 2;
                    MMA_F16(O[nf][0], O[nf][1], O[nf][2], O[nf][3],
                            ph0, ph1, ph2, ph3, v[j][0], v[j][2]);
                    MMA_F16(O[nf+1][0], O[nf+1][1], O[nf+1][2], O[nf+1][3],
                            ph0, ph1, ph2, ph3, v[j][1], v[j][3]);
                }
            }
        }
    };

    for (int w = 0; w < nwin; w++) {
        if (w < nwin - 1) cp_wait<1>(); else cp_wait<0>();
        __syncthreads();

        const uint32_t sb = smb + (w & 1) * STAGEB;
        const int kc = kc0 + w * 128;

        do_chunk(kc, sb);
        do_chunk(kc + 64, sb + TILEB);

        __syncthreads();
        if (w + 2 < nwin) load_window(kc0 + (w + 2) * 128, w & 1);
    }

    // ---- epilogue ----
    l0 += __shfl_xor_sync(0xffffffffu, l0, 1);
    l0 += __shfl_xor_sync(0xffffffffu, l0, 2);
    l1 += __shfl_xor_sync(0xffffffffu, l1, 1);
    l1 += __shfl_xor_sync(0xffffffffu, l1, 2);
    float inv0 = 1.f / l0, inv1 = 1.f / l1;

    size_t out0 = ((size_t)(b * SS + qpos0) * DIM) + head * 64;
    size_t out1 = out0 + (size_t)8 * DIM;
#pragma unroll
    for (int nf = 0; nf < 8; nf++) {
        float y0 = O[nf][0] * inv0, y1 = O[nf][1] * inv0;
        float y2 = O[nf][2] * inv1, y3 = O[nf][3] * inv1;
        int col = nf * 8 + c2;
        *(uint32_t*)(g_ah + out0 + col) = packh(y0, y1);
        *(uint32_t*)(g_ah + out1 + col) = packh(y2, y3);
    }
}

// ---------------- launch ----------------
extern "C" void kernel_launch(void* const* d_in, const int* in_sizes, int n_in,
                              void* d_out, int out_size)
{
    const float* x  = (const float*)d_in[0];
    const float* wq = (const float*)d_in[1];
    const float* wk = (const float*)d_in[2];
    const float* wv = (const float*)d_in[3];
    const float* wo = (const float*)d_in[4];
    const float* qw = (const float*)d_in[5];
    const float* kw = (const float*)d_in[6];
    float* out = (float*)d_out;

    __half *qkvh = nullptr, *ah = nullptr, *wh = nullptr;
    cudaGetSymbolAddress((void**)&qkvh, g_qkvh);
    cudaGetSymbolAddress((void**)&ah, g_ah);
    cudaGetSymbolAddress((void**)&wh, g_wh);

    static bool attr_done = false;
    if (!attr_done) {
        cudaFuncSetAttribute(hmma_gemm, cudaFuncAttributeMaxDynamicSharedMemorySize, GEMM_SMEM);
        cudaFuncSetAttribute(attn_tc, cudaFuncAttributeMaxDynamicSharedMemorySize, ATT_SMEM);
        attr_done = true;
    }

    split_all<<<(1048576 + 655360) / 256, 256>>>(x, wq, wk, wv, wo);
    hmma_gemm<<<dim3(QKVW / 64, TT / 128), 256, GEMM_SMEM>>>(ah, wh, qkvh, QKVW, 0, 1);
    prep_qkv<<<TT, 256>>>(qw, kw);
    attn_tc<<<dim3(SS / 128, NH, BB), 256, ATT_SMEM>>>();
    hmma_gemm<<<dim3(DIM / 64, TT / 128), 256, GEMM_SMEM>>>(
        ah, wh + (size_t)WO_ROW * DIM, out, DIM, 0, 0);
}